// round 3
// baseline (speedup 1.0000x reference)
#include <cuda_runtime.h>
#include <cuda_bf16.h>

#define NN 10000
#define NE 80000

// ---------------- scratch (static device memory, no allocs) ----------------
__device__ int   g_deg[NN];
__device__ int   g_offs[NN + 1];
__device__ int   g_cursor[NN];
__device__ int   g_csr[NE];
__device__ float g_h1e[NE * 25];      // relu(ea@nn1_w1+b1)
__device__ float g_h2e[NE * 25];      // relu(ea@nn2_w1+b2_1)
__device__ float g_A1[NN * 432];      // [S1/deg | Xsum1/deg | x]
__device__ float g_A2[NN * 864];      // [S2/deg | Hsum/deg | h1]
__device__ float g_W1[432 * 32];      // [w2_re ; b2_re ; root]
__device__ float g_W2[864 * 64];
__device__ float g_t1[NN * 32];
__device__ float g_h1[NN * 32];
__device__ float g_t2[NN * 64];
__device__ float g_h2[NN * 64];
__device__ float g_bn[256];           // sum1[0:32] sq1[64:96] sum2[128:192] sq2[192:256]
__device__ float g_scale[64];
__device__ float g_shift[64];

__device__ __forceinline__ float eluf(float x) { return x > 0.f ? x : expm1f(x); }

// ---------------- init ----------------
__global__ void k_init(float* out) {
    int i = blockIdx.x * blockDim.x + threadIdx.x;
    if (i < NN) g_deg[i] = 0;
    if (i < 256) g_bn[i] = 0.f;
    if (i == 0) out[0] = 0.f;
}

// ---------------- degree histogram ----------------
__global__ void k_deg(const int* __restrict__ ei) {
    int e = blockIdx.x * blockDim.x + threadIdx.x;
    if (e < NE) atomicAdd(&g_deg[ei[NE + e]], 1);
}

// ---------------- exclusive scan over 10000 degrees (single block) ----------------
__global__ void k_scan() {
    __shared__ int part[1024];
    int t = threadIdx.x;
    int base = t * 10;
    int s = 0;
    if (base < NN) {
        #pragma unroll
        for (int j = 0; j < 10; j++) if (base + j < NN) s += g_deg[base + j];
    }
    part[t] = s;
    __syncthreads();
    for (int off = 1; off < 1024; off <<= 1) {
        int v = 0;
        if (t >= off) v = part[t - off];
        __syncthreads();
        part[t] += v;
        __syncthreads();
    }
    int excl = (t == 0) ? 0 : part[t - 1];
    if (base < NN) {
        int run = excl;
        #pragma unroll
        for (int j = 0; j < 10; j++) {
            if (base + j < NN) {
                g_offs[base + j] = run;
                g_cursor[base + j] = run;
                run += g_deg[base + j];
            }
        }
    }
    if (t == 1023) g_offs[NN] = part[1023];
}

// ---------------- CSR fill ----------------
__global__ void k_fill(const int* __restrict__ ei) {
    int e = blockIdx.x * blockDim.x + threadIdx.x;
    if (e < NE) {
        int d = ei[NE + e];
        int pos = atomicAdd(&g_cursor[d], 1);
        g_csr[pos] = e;
    }
}

// ---------------- fused edge MLP hidden layers (both convs) ----------------
__global__ void k_edgemlp(const float* __restrict__ ea,
                          const float* __restrict__ w1a, const float* __restrict__ b1a,
                          const float* __restrict__ w1b, const float* __restrict__ b1b) {
    __shared__ float sA[225];  // [0:200) w1a, [200:225) b1a
    __shared__ float sB[225];
    int tid = threadIdx.x;
    for (int l = tid; l < 225; l += blockDim.x) {
        sA[l] = (l < 200) ? w1a[l] : b1a[l - 200];
        sB[l] = (l < 200) ? w1b[l] : b1b[l - 200];
    }
    __syncthreads();
    int e = blockIdx.x * blockDim.x + tid;
    if (e >= NE) return;
    float a[8];
    #pragma unroll
    for (int i = 0; i < 8; i++) a[i] = ea[e * 8 + i];
    #pragma unroll
    for (int k = 0; k < 25; k++) {
        float s = sA[200 + k];
        #pragma unroll
        for (int i = 0; i < 8; i++) s += a[i] * sA[i * 25 + k];
        g_h1e[e * 25 + k] = fmaxf(s, 0.f);
    }
    #pragma unroll
    for (int k = 0; k < 25; k++) {
        float s = sB[200 + k];
        #pragma unroll
        for (int i = 0; i < 8; i++) s += a[i] * sB[i * 25 + k];
        g_h2e[e * 25 + k] = fmaxf(s, 0.f);
    }
}

// ---------------- build augmented weight matrix [25*CIN + 2*CIN, COUT] ----------------
template <int CIN, int COUT>
__global__ void k_prepW(const float* __restrict__ w2, const float* __restrict__ b2,
                        const float* __restrict__ root, float* __restrict__ W) {
    constexpr int KA = 25 * CIN + 2 * CIN;
    int idx = blockIdx.x * blockDim.x + threadIdx.x;
    if (idx >= KA * COUT) return;
    int kidx = idx / COUT, o = idx % COUT;
    float v;
    if (kidx < 25 * CIN) {
        int k = kidx / CIN, i = kidx % CIN;
        v = w2[(k * CIN + i) * COUT + o];
    } else if (kidx < 25 * CIN + CIN) {
        int i = kidx - 25 * CIN;
        v = b2[i * COUT + o];
    } else {
        int i = kidx - 25 * CIN - CIN;
        v = root[i * COUT + o];
    }
    W[idx] = v;
}

// ---------------- per-node gather of rank-1 outer products (CSR, no atomics) -------
template <int CIN>
__global__ void __launch_bounds__(256) k_gather(const int* __restrict__ ei,
                                                const float* __restrict__ xfeat,
                                                const float* __restrict__ hE,
                                                float* __restrict__ A) {
    constexpr int SW = 25 * CIN;
    constexpr int KA = SW + 2 * CIN;
    constexpr int NACC = (SW + 255) / 256;
    int n = blockIdx.x;
    int t = threadIdx.x;
    __shared__ float sh[25 + CIN];
    float acc[NACC];
    #pragma unroll
    for (int j = 0; j < NACC; j++) acc[j] = 0.f;
    float xs = 0.f;
    int e0 = g_offs[n], e1 = g_offs[n + 1];
    for (int p = e0; p < e1; p++) {
        int e = g_csr[p];
        if (t < 25) sh[t] = hE[e * 25 + t];
        else if (t < 25 + CIN) sh[t] = xfeat[ei[e] * CIN + (t - 25)];
        __syncthreads();
        #pragma unroll
        for (int j = 0; j < NACC; j++) {
            int idx = t + j * 256;
            if (idx < SW) acc[j] += sh[idx / CIN] * sh[25 + (idx % CIN)];
        }
        if (t < CIN) xs += sh[25 + t];
        __syncthreads();
    }
    float inv = 1.f / fmaxf((float)(e1 - e0), 1.f);
    #pragma unroll
    for (int j = 0; j < NACC; j++) {
        int idx = t + j * 256;
        if (idx < SW) A[n * KA + idx] = acc[j] * inv;
    }
    if (t < CIN) {
        A[n * KA + SW + t] = xs * inv;
        A[n * KA + SW + CIN + t] = xfeat[n * CIN + t];
    }
}

// ---------------- dense GEMM  out = elu(A[NN,KA] @ W[KA,COUT] + bias) ----------------
template <int KA, int COUT>
__global__ void __launch_bounds__(256) k_gemm(const float* __restrict__ A,
                                              const float* __restrict__ W,
                                              const float* __restrict__ bias,
                                              float* __restrict__ out) {
    constexpr int TN = COUT / 16;  // 2 or 4
    constexpr int BM = 64, BK = 8;
    __shared__ float As[BM][BK];
    __shared__ float Bs[BK][COUT];
    int tid = threadIdx.x;
    int tx = tid & 15, ty = tid >> 4;
    int row0 = blockIdx.x * BM;
    float acc[4][TN];
    #pragma unroll
    for (int m = 0; m < 4; m++)
        #pragma unroll
        for (int j = 0; j < TN; j++) acc[m][j] = 0.f;

    for (int k0 = 0; k0 < KA; k0 += BK) {
        for (int l = tid; l < BM * BK; l += 256) {
            int r = l >> 3, kk = l & 7;
            int gr = row0 + r;
            As[r][kk] = (gr < NN) ? A[gr * KA + k0 + kk] : 0.f;
        }
        for (int l = tid; l < BK * COUT; l += 256) {
            int kk = l / COUT, o = l % COUT;
            Bs[kk][o] = W[(k0 + kk) * COUT + o];
        }
        __syncthreads();
        #pragma unroll
        for (int kk = 0; kk < BK; kk++) {
            float b[TN];
            #pragma unroll
            for (int j = 0; j < TN; j++) b[j] = Bs[kk][tx * TN + j];
            #pragma unroll
            for (int m = 0; m < 4; m++) {
                float a = As[ty * 4 + m][kk];
                #pragma unroll
                for (int j = 0; j < TN; j++) acc[m][j] += a * b[j];
            }
        }
        __syncthreads();
    }
    #pragma unroll
    for (int m = 0; m < 4; m++) {
        int n = row0 + ty * 4 + m;
        if (n >= NN) continue;
        #pragma unroll
        for (int j = 0; j < TN; j++) {
            int o = tx * TN + j;
            float v = acc[m][j] + bias[o];
            out[n * COUT + o] = eluf(v);
        }
    }
}

// ---------------- batchnorm stats ----------------
template <int C>
__global__ void k_bnstats(const float* __restrict__ t, float* __restrict__ sum,
                          float* __restrict__ sq) {
    constexpr int G = 256 / C;
    int tid = threadIdx.x;
    int c = tid % C, g = tid / C;
    float s = 0.f, q = 0.f;
    for (int r = blockIdx.x * G + g; r < NN; r += gridDim.x * G) {
        float v = t[r * C + c];
        s += v;
        q += v * v;
    }
    __shared__ float ss[256], qq[256];
    ss[tid] = s;
    qq[tid] = q;
    __syncthreads();
    if (g == 0) {
        #pragma unroll
        for (int gg = 1; gg < G; gg++) {
            s += ss[gg * C + c];
            q += qq[gg * C + c];
        }
        atomicAdd(&sum[c], s);
        atomicAdd(&sq[c], q);
    }
}

__global__ void k_bnfin(const float* __restrict__ sum, const float* __restrict__ sq,
                        const float* __restrict__ gamma, const float* __restrict__ beta,
                        int C) {
    int c = threadIdx.x;
    if (c < C) {
        float m = sum[c] / (float)NN;
        float v = sq[c] / (float)NN - m * m;
        float inv = rsqrtf(v + 1e-5f);
        g_scale[c] = inv * gamma[c];
        g_shift[c] = beta[c] - m * inv * gamma[c];
    }
}

template <int C>
__global__ void k_bnapply(const float* __restrict__ t, float* __restrict__ h) {
    int idx = blockIdx.x * blockDim.x + threadIdx.x;
    if (idx < NN * C) {
        int c = idx % C;
        float v = t[idx] * g_scale[c] + g_shift[c];
        h[idx] = eluf(v);
    }
}

// ---------------- FC head + global sum ----------------
__global__ void __launch_bounds__(128) k_fc(const float* __restrict__ h,
                                            const float* __restrict__ w1,
                                            const float* __restrict__ b1,
                                            const float* __restrict__ w2,
                                            const float* __restrict__ b2,
                                            float* __restrict__ out) {
    __shared__ float sw[64 * 128];
    __shared__ float sh[64];
    __shared__ float sred[128];
    int tid = threadIdx.x;
    for (int l = tid; l < 64 * 128; l += 128) sw[l] = w1[l];
    float myb = b1[tid];
    float myw2 = w2[tid];
    float local = 0.f;
    __syncthreads();
    for (int n = blockIdx.x; n < NN; n += gridDim.x) {
        if (tid < 64) sh[tid] = h[n * 64 + tid];
        __syncthreads();
        float s = myb;
        #pragma unroll
        for (int i = 0; i < 64; i++) s += sh[i] * sw[i * 128 + tid];
        s = eluf(s);
        sred[tid] = s * myw2;
        __syncthreads();
        for (int off = 64; off > 0; off >>= 1) {
            if (tid < off) sred[tid] += sred[tid + off];
            __syncthreads();
        }
        if (tid == 0) {
            float y = sred[0] + b2[0];
            local += eluf(y);
        }
        __syncthreads();
    }
    if (tid == 0) atomicAdd(out, local);
}

// ---------------- launch ----------------
extern "C" void kernel_launch(void* const* d_in, const int* in_sizes, int n_in,
                              void* d_out, int out_size) {
    const float* x        = (const float*)d_in[0];
    const int*   ei       = (const int*)d_in[1];
    const float* ea       = (const float*)d_in[2];
    const float* nn1_w1   = (const float*)d_in[3];
    const float* nn1_b1   = (const float*)d_in[4];
    const float* nn1_w2   = (const float*)d_in[5];
    const float* nn1_b2   = (const float*)d_in[6];
    const float* c1_root  = (const float*)d_in[7];
    const float* c1_bias  = (const float*)d_in[8];
    const float* bn1_g    = (const float*)d_in[9];
    const float* bn1_b    = (const float*)d_in[10];
    const float* nn2_w1   = (const float*)d_in[11];
    const float* nn2_b1   = (const float*)d_in[12];
    const float* nn2_w2   = (const float*)d_in[13];
    const float* nn2_b2   = (const float*)d_in[14];
    const float* c2_root  = (const float*)d_in[15];
    const float* c2_bias  = (const float*)d_in[16];
    const float* bn2_g    = (const float*)d_in[17];
    const float* bn2_b    = (const float*)d_in[18];
    const float* fc1_w    = (const float*)d_in[19];
    const float* fc1_b    = (const float*)d_in[20];
    const float* fc2_w    = (const float*)d_in[21];
    const float* fc2_b    = (const float*)d_in[22];
    float* out = (float*)d_out;

    float *pA1, *pA2, *pW1, *pW2, *ph1e, *ph2e, *pt1, *ph1, *pt2, *ph2, *pbn;
    cudaGetSymbolAddress((void**)&pA1, g_A1);
    cudaGetSymbolAddress((void**)&pA2, g_A2);
    cudaGetSymbolAddress((void**)&pW1, g_W1);
    cudaGetSymbolAddress((void**)&pW2, g_W2);
    cudaGetSymbolAddress((void**)&ph1e, g_h1e);
    cudaGetSymbolAddress((void**)&ph2e, g_h2e);
    cudaGetSymbolAddress((void**)&pt1, g_t1);
    cudaGetSymbolAddress((void**)&ph1, g_h1);
    cudaGetSymbolAddress((void**)&pt2, g_t2);
    cudaGetSymbolAddress((void**)&ph2, g_h2);
    cudaGetSymbolAddress((void**)&pbn, g_bn);

    k_init<<<(NN + 255) / 256, 256>>>(out);
    k_deg<<<(NE + 255) / 256, 256>>>(ei);
    k_scan<<<1, 1024>>>();
    k_fill<<<(NE + 255) / 256, 256>>>(ei);
    k_edgemlp<<<(NE + 255) / 256, 256>>>(ea, nn1_w1, nn1_b1, nn2_w1, nn2_b1);
    k_prepW<16, 32><<<(432 * 32 + 255) / 256, 256>>>(nn1_w2, nn1_b2, c1_root, pW1);
    k_prepW<32, 64><<<(864 * 64 + 255) / 256, 256>>>(nn2_w2, nn2_b2, c2_root, pW2);

    // conv1
    k_gather<16><<<NN, 256>>>(ei, x, ph1e, pA1);
    k_gemm<432, 32><<<(NN + 63) / 64, 256>>>(pA1, pW1, c1_bias, pt1);
    k_bnstats<32><<<64, 256>>>(pt1, pbn + 0, pbn + 64);
    k_bnfin<<<1, 64>>>(pbn + 0, pbn + 64, bn1_g, bn1_b, 32);
    k_bnapply<32><<<(NN * 32 + 255) / 256, 256>>>(pt1, ph1);

    // conv2
    k_gather<32><<<NN, 256>>>(ei, ph1, ph2e, pA2);
    k_gemm<864, 64><<<(NN + 63) / 64, 256>>>(pA2, pW2, c2_bias, pt2);
    k_bnstats<64><<<64, 256>>>(pt2, pbn + 128, pbn + 192);
    k_bnfin<<<1, 64>>>(pbn + 128, pbn + 192, bn2_g, bn2_b, 64);
    k_bnapply<64><<<(NN * 64 + 255) / 256, 256>>>(pt2, ph2);

    // head
    k_fc<<<592, 128>>>(ph2, fc1_w, fc1_b, fc2_w, fc2_b, out);
}

// round 5
// speedup vs baseline: 1.7241x; 1.7241x over previous
#include <cuda_runtime.h>
#include <cuda_bf16.h>

#define NN 10000
#define NE 80000

// ---------------- scratch (static device memory, no allocs) ----------------
__device__ int   g_deg[NN];
__device__ int   g_offs[NN + 1];
__device__ int   g_cursor[NN];
__device__ int   g_csr[NE];
__device__ float g_h1e[NE * 25];      // relu(ea@nn1_w1+b1)
__device__ float g_h2e[NE * 25];      // relu(ea@nn2_w1+b2_1)
__device__ float g_A1[NN * 432];      // [S1/deg | Xsum1/deg | x]
__device__ float g_A2[NN * 864];      // [S2/deg | Hsum/deg | h1]
__device__ float g_W1[432 * 32];      // [w2_re ; b2_re ; root]
__device__ float g_W2[864 * 64];
__device__ float g_t1[NN * 32];
__device__ float g_h1[NN * 32];
__device__ float g_t2[NN * 64];
__device__ float g_h2[NN * 64];
__device__ float g_bn[256];           // sum1[0:32] sq1[64:96] sum2[128:192] sq2[192:256]
__device__ float g_scale[64];
__device__ float g_shift[64];

__device__ __forceinline__ float eluf(float x) { return x > 0.f ? x : expm1f(x); }

// ---- packed f32x2 helpers (Blackwell FFMA2: 2x fp32 throughput) ----
typedef unsigned long long ull;
__device__ __forceinline__ ull pack2(float lo, float hi) {
    ull d; asm("mov.b64 %0, {%1, %2};" : "=l"(d) : "f"(lo), "f"(hi)); return d;
}
__device__ __forceinline__ void unpack2(ull v, float& lo, float& hi) {
    asm("mov.b64 {%0, %1}, %2;" : "=f"(lo), "=f"(hi) : "l"(v));
}
__device__ __forceinline__ ull ffma2(ull a, ull b, ull c) {
    ull d; asm("fma.rn.f32x2 %0, %1, %2, %3;" : "=l"(d) : "l"(a), "l"(b), "l"(c)); return d;
}

// ---------------- init ----------------
__global__ void k_init(float* out) {
    int i = blockIdx.x * blockDim.x + threadIdx.x;
    if (i < NN) g_deg[i] = 0;
    if (i < 256) g_bn[i] = 0.f;
    if (i == 0) out[0] = 0.f;
}

// ---------------- degree histogram ----------------
__global__ void k_deg(const int* __restrict__ ei) {
    int e = blockIdx.x * blockDim.x + threadIdx.x;
    if (e < NE) atomicAdd(&g_deg[ei[NE + e]], 1);
}

// ---------------- exclusive scan over 10000 degrees (single block) ----------------
__global__ void k_scan() {
    __shared__ int part[1024];
    int t = threadIdx.x;
    int base = t * 10;
    int s = 0;
    if (base < NN) {
        #pragma unroll
        for (int j = 0; j < 10; j++) if (base + j < NN) s += g_deg[base + j];
    }
    part[t] = s;
    __syncthreads();
    for (int off = 1; off < 1024; off <<= 1) {
        int v = 0;
        if (t >= off) v = part[t - off];
        __syncthreads();
        part[t] += v;
        __syncthreads();
    }
    int excl = (t == 0) ? 0 : part[t - 1];
    if (base < NN) {
        int run = excl;
        #pragma unroll
        for (int j = 0; j < 10; j++) {
            if (base + j < NN) {
                g_offs[base + j] = run;
                g_cursor[base + j] = run;
                run += g_deg[base + j];
            }
        }
    }
    if (t == 1023) g_offs[NN] = part[1023];
}

// ---------------- CSR fill ----------------
__global__ void k_fill(const int* __restrict__ ei) {
    int e = blockIdx.x * blockDim.x + threadIdx.x;
    if (e < NE) {
        int d = ei[NE + e];
        int pos = atomicAdd(&g_cursor[d], 1);
        g_csr[pos] = e;
    }
}

// ---------------- fused edge MLP hidden layers (both convs) ----------------
__global__ void k_edgemlp(const float* __restrict__ ea,
                          const float* __restrict__ w1a, const float* __restrict__ b1a,
                          const float* __restrict__ w1b, const float* __restrict__ b1b) {
    __shared__ float sA[225];
    __shared__ float sB[225];
    int tid = threadIdx.x;
    for (int l = tid; l < 225; l += blockDim.x) {
        sA[l] = (l < 200) ? w1a[l] : b1a[l - 200];
        sB[l] = (l < 200) ? w1b[l] : b1b[l - 200];
    }
    __syncthreads();
    int e = blockIdx.x * blockDim.x + tid;
    if (e >= NE) return;
    float a[8];
    #pragma unroll
    for (int i = 0; i < 8; i++) a[i] = ea[e * 8 + i];
    #pragma unroll
    for (int k = 0; k < 25; k++) {
        float s = sA[200 + k];
        #pragma unroll
        for (int i = 0; i < 8; i++) s += a[i] * sA[i * 25 + k];
        g_h1e[e * 25 + k] = fmaxf(s, 0.f);
    }
    #pragma unroll
    for (int k = 0; k < 25; k++) {
        float s = sB[200 + k];
        #pragma unroll
        for (int i = 0; i < 8; i++) s += a[i] * sB[i * 25 + k];
        g_h2e[e * 25 + k] = fmaxf(s, 0.f);
    }
}

// ---------------- build augmented weight matrix [25*CIN + 2*CIN, COUT] ----------------
template <int CIN, int COUT>
__global__ void k_prepW(const float* __restrict__ w2, const float* __restrict__ b2,
                        const float* __restrict__ root, float* __restrict__ W) {
    constexpr int KA = 25 * CIN + 2 * CIN;
    int idx = blockIdx.x * blockDim.x + threadIdx.x;
    if (idx >= KA * COUT) return;
    int kidx = idx / COUT, o = idx % COUT;
    float v;
    if (kidx < 25 * CIN) {
        int k = kidx / CIN, i = kidx % CIN;
        v = w2[(k * CIN + i) * COUT + o];
    } else if (kidx < 25 * CIN + CIN) {
        int i = kidx - 25 * CIN;
        v = b2[i * COUT + o];
    } else {
        int i = kidx - 25 * CIN - CIN;
        v = root[i * COUT + o];
    }
    W[idx] = v;
}

// ------- per-node gather of rank-1 outer products, batched edges (EB per barrier) ----
template <int CIN>
__global__ void __launch_bounds__(256) k_gather(const int* __restrict__ ei,
                                                const float* __restrict__ xfeat,
                                                const float* __restrict__ hE,
                                                float* __restrict__ A) {
    constexpr int SW = 25 * CIN;
    constexpr int KA = SW + 2 * CIN;
    constexpr int NACC = (SW + 255) / 256;
    constexpr int EB = 8;
    constexpr int EW = 25 + CIN;
    constexpr int LOADS = EB * EW;
    int n = blockIdx.x;
    int t = threadIdx.x;
    __shared__ float shh[EB][25];
    __shared__ float shx[EB][CIN];
    float acc[NACC];
    #pragma unroll
    for (int j = 0; j < NACC; j++) acc[j] = 0.f;
    float xs = 0.f;
    int e0 = g_offs[n], e1 = g_offs[n + 1];

    for (int p0 = e0; p0 < e1; p0 += EB) {
        int cnt = e1 - p0; if (cnt > EB) cnt = EB;
        #pragma unroll
        for (int l = t; l < LOADS; l += 256) {
            int j = l / EW, r = l - j * EW;
            float v = 0.f;
            if (j < cnt) {
                int e = __ldg(&g_csr[p0 + j]);
                if (r < 25) v = hE[e * 25 + r];
                else        v = xfeat[__ldg(&ei[e]) * CIN + (r - 25)];
            }
            if (r < 25) shh[j][r] = v;
            else        shx[j][r - 25] = v;
        }
        __syncthreads();
        #pragma unroll
        for (int j = 0; j < EB; j++) {
            #pragma unroll
            for (int na = 0; na < NACC; na++) {
                int idx = t + na * 256;
                if (idx < SW) acc[na] += shh[j][idx / CIN] * shx[j][idx % CIN];
            }
        }
        if (t < CIN) {
            #pragma unroll
            for (int j = 0; j < EB; j++) xs += shx[j][t];
        }
        __syncthreads();
    }
    float inv = 1.f / fmaxf((float)(e1 - e0), 1.f);
    #pragma unroll
    for (int na = 0; na < NACC; na++) {
        int idx = t + na * 256;
        if (idx < SW) A[n * KA + idx] = acc[na] * inv;
    }
    if (t < CIN) {
        A[n * KA + SW + t] = xs * inv;
        A[n * KA + SW + CIN + t] = xfeat[n * CIN + t];
    }
}

// ------- dense GEMM  out = elu(A[NN,KA] @ W[KA,COUT] + bias), packed f32x2 FMA -------
template <int KA, int COUT, int BK>
__global__ void __launch_bounds__(256) k_gemm(const float* __restrict__ A,
                                              const float* __restrict__ W,
                                              const float* __restrict__ bias,
                                              float* __restrict__ out) {
    constexpr int BM = 64;
    constexpr int TC = COUT / 16;   // cols per thread (2 or 4)
    constexpr int NP = TC / 2;      // f32x2 pairs (1 or 2)
    __shared__ float As[BK][BM];
    __shared__ float Bs[BK * COUT];
    int tid = threadIdx.x;
    int tx = tid & 15, ty = tid >> 4;
    int row0 = blockIdx.x * BM;

    ull acc[4][NP];
    #pragma unroll
    for (int m = 0; m < 4; m++)
        #pragma unroll
        for (int p = 0; p < NP; p++) acc[m][p] = 0ull;

    for (int k0 = 0; k0 < KA; k0 += BK) {
        // A tile: coalesced float4 loads, transposed scalar stores
        constexpr int AF4 = BM * BK / 4;
        #pragma unroll
        for (int l = tid; l < AF4; l += 256) {
            int r = l / (BK / 4), q = l % (BK / 4);
            int gr = row0 + r;
            float4 v = make_float4(0.f, 0.f, 0.f, 0.f);
            if (gr < NN) v = *(const float4*)&A[gr * KA + k0 + q * 4];
            As[q * 4 + 0][r] = v.x;
            As[q * 4 + 1][r] = v.y;
            As[q * 4 + 2][r] = v.z;
            As[q * 4 + 3][r] = v.w;
        }
        // B tile: contiguous float4 copy
        constexpr int BF4 = BK * COUT / 4;
        const float4* Wp = (const float4*)&W[k0 * COUT];
        #pragma unroll
        for (int l = tid; l < BF4; l += 256) ((float4*)Bs)[l] = Wp[l];
        __syncthreads();

        #pragma unroll
        for (int kk = 0; kk < BK; kk++) {
            ull bp[NP];
            if (NP == 2) {
                float4 bq = *(const float4*)&Bs[kk * COUT + tx * 4];
                bp[0] = pack2(bq.x, bq.y);
                bp[1] = pack2(bq.z, bq.w);
            } else {
                float2 bq = *(const float2*)&Bs[kk * COUT + tx * 2];
                bp[0] = pack2(bq.x, bq.y);
            }
            float4 a4 = *(const float4*)&As[kk][ty * 4];
            ull aa0 = pack2(a4.x, a4.x);
            ull aa1 = pack2(a4.y, a4.y);
            ull aa2 = pack2(a4.z, a4.z);
            ull aa3 = pack2(a4.w, a4.w);
            #pragma unroll
            for (int p = 0; p < NP; p++) {
                acc[0][p] = ffma2(aa0, bp[p], acc[0][p]);
                acc[1][p] = ffma2(aa1, bp[p], acc[1][p]);
                acc[2][p] = ffma2(aa2, bp[p], acc[2][p]);
                acc[3][p] = ffma2(aa3, bp[p], acc[3][p]);
            }
        }
        __syncthreads();
    }
    #pragma unroll
    for (int m = 0; m < 4; m++) {
        int n = row0 + ty * 4 + m;
        if (n >= NN) continue;
        #pragma unroll
        for (int p = 0; p < NP; p++) {
            float lo, hi;
            unpack2(acc[m][p], lo, hi);
            int o = tx * TC + p * 2;
            out[n * COUT + o]     = eluf(lo + bias[o]);
            out[n * COUT + o + 1] = eluf(hi + bias[o + 1]);
        }
    }
}

// ---------------- batchnorm stats ----------------
template <int C>
__global__ void k_bnstats(const float* __restrict__ t, float* __restrict__ sum,
                          float* __restrict__ sq) {
    constexpr int G = 256 / C;
    int tid = threadIdx.x;
    int c = tid % C, g = tid / C;
    float s = 0.f, q = 0.f;
    for (int r = blockIdx.x * G + g; r < NN; r += gridDim.x * G) {
        float v = t[r * C + c];
        s += v;
        q += v * v;
    }
    __shared__ float ss[256], qq[256];
    ss[tid] = s;
    qq[tid] = q;
    __syncthreads();
    if (g == 0) {
        #pragma unroll
        for (int gg = 1; gg < G; gg++) {
            s += ss[gg * C + c];
            q += qq[gg * C + c];
        }
        atomicAdd(&sum[c], s);
        atomicAdd(&sq[c], q);
    }
}

__global__ void k_bnfin(const float* __restrict__ sum, const float* __restrict__ sq,
                        const float* __restrict__ gamma, const float* __restrict__ beta,
                        int C) {
    int c = threadIdx.x;
    if (c < C) {
        float m = sum[c] / (float)NN;
        float v = sq[c] / (float)NN - m * m;
        float inv = rsqrtf(v + 1e-5f);
        g_scale[c] = inv * gamma[c];
        g_shift[c] = beta[c] - m * inv * gamma[c];
    }
}

template <int C>
__global__ void k_bnapply(const float* __restrict__ t, float* __restrict__ h) {
    int idx = blockIdx.x * blockDim.x + threadIdx.x;
    if (idx < NN * C) {
        int c = idx % C;
        float v = t[idx] * g_scale[c] + g_shift[c];
        h[idx] = eluf(v);
    }
}

// ---------------- FC head + global sum: warp-per-node, shuffle reduce ----------------
__global__ void __launch_bounds__(256) k_fc(const float* __restrict__ h,
                                            const float* __restrict__ w1,
                                            const float* __restrict__ b1,
                                            const float* __restrict__ w2,
                                            const float* __restrict__ b2,
                                            float* __restrict__ out) {
    __shared__ float sw[64 * 128];
    int tid = threadIdx.x;
    int lane = tid & 31, warp = tid >> 5;
    #pragma unroll
    for (int l = tid; l < 64 * 128 / 4; l += 256)
        ((float4*)sw)[l] = ((const float4*)w1)[l];
    float b1v[4], w2v[4];
    #pragma unroll
    for (int j = 0; j < 4; j++) {
        b1v[j] = b1[j * 32 + lane];
        w2v[j] = w2[j * 32 + lane];
    }
    float b2v = b2[0];
    __syncthreads();

    float local = 0.f;
    for (int n = blockIdx.x * 8 + warp; n < NN; n += gridDim.x * 8) {
        float hv0 = h[n * 64 + lane];
        float hv1 = h[n * 64 + 32 + lane];
        float s0 = b1v[0], s1 = b1v[1], s2 = b1v[2], s3 = b1v[3];
        #pragma unroll
        for (int i = 0; i < 64; i++) {
            float hv = __shfl_sync(0xffffffffu, (i < 32) ? hv0 : hv1, i & 31);
            s0 += hv * sw[i * 128 + lane];
            s1 += hv * sw[i * 128 + 32 + lane];
            s2 += hv * sw[i * 128 + 64 + lane];
            s3 += hv * sw[i * 128 + 96 + lane];
        }
        float contrib = eluf(s0) * w2v[0] + eluf(s1) * w2v[1]
                      + eluf(s2) * w2v[2] + eluf(s3) * w2v[3];
        #pragma unroll
        for (int off = 16; off > 0; off >>= 1)
            contrib += __shfl_xor_sync(0xffffffffu, contrib, off);
        if (lane == 0) local += eluf(contrib + b2v);
    }
    if (lane == 0) atomicAdd(out, local);
}

// ---------------- launch ----------------
extern "C" void kernel_launch(void* const* d_in, const int* in_sizes, int n_in,
                              void* d_out, int out_size) {
    const float* x        = (const float*)d_in[0];
    const int*   ei       = (const int*)d_in[1];
    const float* ea       = (const float*)d_in[2];
    const float* nn1_w1   = (const float*)d_in[3];
    const float* nn1_b1   = (const float*)d_in[4];
    const float* nn1_w2   = (const float*)d_in[5];
    const float* nn1_b2   = (const float*)d_in[6];
    const float* c1_root  = (const float*)d_in[7];
    const float* c1_bias  = (const float*)d_in[8];
    const float* bn1_g    = (const float*)d_in[9];
    const float* bn1_b    = (const float*)d_in[10];
    const float* nn2_w1   = (const float*)d_in[11];
    const float* nn2_b1   = (const float*)d_in[12];
    const float* nn2_w2   = (const float*)d_in[13];
    const float* nn2_b2   = (const float*)d_in[14];
    const float* c2_root  = (const float*)d_in[15];
    const float* c2_bias  = (const float*)d_in[16];
    const float* bn2_g    = (const float*)d_in[17];
    const float* bn2_b    = (const float*)d_in[18];
    const float* fc1_w    = (const float*)d_in[19];
    const float* fc1_b    = (const float*)d_in[20];
    const float* fc2_w    = (const float*)d_in[21];
    const float* fc2_b    = (const float*)d_in[22];
    float* out = (float*)d_out;

    float *pA1, *pA2, *pW1, *pW2, *ph1e, *ph2e, *pt1, *ph1, *pt2, *ph2, *pbn;
    cudaGetSymbolAddress((void**)&pA1, g_A1);
    cudaGetSymbolAddress((void**)&pA2, g_A2);
    cudaGetSymbolAddress((void**)&pW1, g_W1);
    cudaGetSymbolAddress((void**)&pW2, g_W2);
    cudaGetSymbolAddress((void**)&ph1e, g_h1e);
    cudaGetSymbolAddress((void**)&ph2e, g_h2e);
    cudaGetSymbolAddress((void**)&pt1, g_t1);
    cudaGetSymbolAddress((void**)&ph1, g_h1);
    cudaGetSymbolAddress((void**)&pt2, g_t2);
    cudaGetSymbolAddress((void**)&ph2, g_h2);
    cudaGetSymbolAddress((void**)&pbn, g_bn);

    k_init<<<(NN + 255) / 256, 256>>>(out);
    k_deg<<<(NE + 255) / 256, 256>>>(ei);
    k_scan<<<1, 1024>>>();
    k_fill<<<(NE + 255) / 256, 256>>>(ei);
    k_edgemlp<<<(NE + 255) / 256, 256>>>(ea, nn1_w1, nn1_b1, nn2_w1, nn2_b1);
    k_prepW<16, 32><<<(432 * 32 + 255) / 256, 256>>>(nn1_w2, nn1_b2, c1_root, pW1);
    k_prepW<32, 64><<<(864 * 64 + 255) / 256, 256>>>(nn2_w2, nn2_b2, c2_root, pW2);

    // conv1
    k_gather<16><<<NN, 256>>>(ei, x, ph1e, pA1);
    k_gemm<432, 32, 16><<<(NN + 63) / 64, 256>>>(pA1, pW1, c1_bias, pt1);
    k_bnstats<32><<<64, 256>>>(pt1, pbn + 0, pbn + 64);
    k_bnfin<<<1, 64>>>(pbn + 0, pbn + 64, bn1_g, bn1_b, 32);
    k_bnapply<32><<<(NN * 32 + 255) / 256, 256>>>(pt1, ph1);

    // conv2
    k_gather<32><<<NN, 256>>>(ei, ph1, ph2e, pA2);
    k_gemm<864, 64, 32><<<(NN + 63) / 64, 256>>>(pA2, pW2, c2_bias, pt2);
    k_bnstats<64><<<64, 256>>>(pt2, pbn + 128, pbn + 192);
    k_bnfin<<<1, 64>>>(pbn + 128, pbn + 192, bn2_g, bn2_b, 64);
    k_bnapply<64><<<(NN * 64 + 255) / 256, 256>>>(pt2, ph2);

    // head
    k_fc<<<148, 256>>>(ph2, fc1_w, fc1_b, fc2_w, fc2_b, out);
}